// round 1
// baseline (speedup 1.0000x reference)
#include <cuda_runtime.h>
#include <math.h>

#define Bsz 1024
#define Dd  512
#define Nn  16
#define Hh  512
#define M_TOT (Bsz * Nn)   // 16384

// Scratch (static device memory — allocation-guard safe).
__device__ float g_T[M_TOT * Dd];        // transposed x, later overwritten with "shared"
__device__ float g_Y[M_TOT * Dd];        // h (layer-1 activations)
__device__ float g_logits[M_TOT * Nn];   // full_logits accumulator

static __device__ __forceinline__ float lrelu(float v) {
    return v >= 0.0f ? v : 0.1f * v;
}

// ---- packed f32x2 helpers (sm_103a) ----
static __device__ __forceinline__ unsigned long long pk2(float lo, float hi) {
    unsigned long long r;
    asm("mov.b64 %0, {%1,%2};" : "=l"(r) : "f"(lo), "f"(hi));
    return r;
}
static __device__ __forceinline__ void upk2(unsigned long long v, float &lo, float &hi) {
    asm("mov.b64 {%0,%1}, %2;" : "=f"(lo), "=f"(hi) : "l"(v));
}
static __device__ __forceinline__ void ffma2(unsigned long long &acc,
                                             unsigned long long a,
                                             unsigned long long b) {
    asm("fma.rn.f32x2 %0, %1, %2, %0;" : "+l"(acc) : "l"(a), "l"(b));
}

// ---------------------------------------------------------------------------
// Kernel: transpose x (B, D, N) -> T[m, d] with m = n*B + b
// ---------------------------------------------------------------------------
__global__ void k_transpose(const float* __restrict__ x) {
    __shared__ float sm[Dd * 17];   // pad 17 to kill bank conflicts on strided reads
    int b = blockIdx.x;
    const float4* xp = reinterpret_cast<const float4*>(x + (size_t)b * Dd * Nn);
    // 512*16 floats = 2048 float4
    for (int v = threadIdx.x; v < 2048; v += blockDim.x) {
        float4 q = xp[v];
        int d  = v >> 2;
        int n0 = (v & 3) * 4;
        sm[d * 17 + n0 + 0] = q.x;
        sm[d * 17 + n0 + 1] = q.y;
        sm[d * 17 + n0 + 2] = q.z;
        sm[d * 17 + n0 + 3] = q.w;
    }
    __syncthreads();
    for (int n = 0; n < Nn; n++) {
        float* dst = g_T + (size_t)(n * Bsz + b) * Dd;
        for (int d = threadIdx.x; d < Dd; d += blockDim.x)
            dst[d] = sm[d * 17 + n];
    }
}

// ---------------------------------------------------------------------------
// Kernel: zero the logits accumulator (must run every launch: graph replays)
// ---------------------------------------------------------------------------
__global__ void k_zero() {
    int i = blockIdx.x * blockDim.x + threadIdx.x;
    if (i < M_TOT * Nn) g_logits[i] = 0.0f;
}

// ---------------------------------------------------------------------------
// GEMM: 128x128 block tile, K-step 16, 256 threads, 8x8 microtile (f32x2 packed)
// MODE 0: g_Y = lrelu(g_T @ W + bias)         (W = Ws1, bias = bs1)
// MODE 1: g_T = lrelu(g_Y @ W + bias)         (W = Ws2, bias = bs2)
// MODE 2: per-n group of Wc1: acc = g_T @ Wc1[n]; epilogue
//         s_m += lrelu(acc + bc1[n,h]) * Wc2[n,h]; atomicAdd into g_logits[m,n]
// ---------------------------------------------------------------------------
template <int MODE>
__global__ void __launch_bounds__(256, 2)
k_gemm(const float* __restrict__ W,
       const float* __restrict__ bias,
       const float* __restrict__ wc2) {
    __shared__ float As[16 * 132];   // A stored transposed [k][m], row pad 132
    __shared__ float Bs[16 * 128];   // B stored [k][j]

    const float* A;
    if (MODE == 0)      A = g_T;
    else if (MODE == 1) A = g_Y;
    else                A = g_T;

    int n = (MODE == 2) ? blockIdx.z : 0;
    const float* Bp    = (MODE == 2) ? (W + (size_t)n * Dd * Hh) : W;
    const float* biasp = (MODE == 2) ? (bias + n * Hh) : bias;
    const float* wc2n  = (MODE == 2) ? (wc2 + n * Hh) : wc2;

    int m0 = blockIdx.y * 128;
    int j0 = blockIdx.x * 128;
    int t  = threadIdx.x;
    int tx = t & 15;
    int ty = t >> 4;

    unsigned long long acc[8][4];
#pragma unroll
    for (int i = 0; i < 8; i++)
#pragma unroll
        for (int j = 0; j < 4; j++) acc[i][j] = 0ULL;

    int arow = t >> 2, acg = (t & 3) * 4;     // A: 128 rows x 16 cols, float4 per thread x2
    int brow = t >> 5, bcg = (t & 31) * 4;    // B: 16 rows x 128 cols

    for (int k0 = 0; k0 < Dd; k0 += 16) {
#pragma unroll
        for (int p = 0; p < 2; p++) {
            int row = arow + p * 64;
            float4 q = *reinterpret_cast<const float4*>(
                A + (size_t)(m0 + row) * Dd + k0 + acg);
            As[(acg + 0) * 132 + row] = q.x;
            As[(acg + 1) * 132 + row] = q.y;
            As[(acg + 2) * 132 + row] = q.z;
            As[(acg + 3) * 132 + row] = q.w;
        }
#pragma unroll
        for (int p = 0; p < 2; p++) {
            int row = brow + p * 8;
            float4 q = *reinterpret_cast<const float4*>(
                Bp + (size_t)(k0 + row) * Dd + j0 + bcg);
            *reinterpret_cast<float4*>(&Bs[row * 128 + bcg]) = q;
        }
        __syncthreads();

#pragma unroll
        for (int k = 0; k < 16; k++) {
            float a[8];
            float4 a0 = *reinterpret_cast<const float4*>(&As[k * 132 + ty * 8]);
            float4 a1 = *reinterpret_cast<const float4*>(&As[k * 132 + ty * 8 + 4]);
            a[0] = a0.x; a[1] = a0.y; a[2] = a0.z; a[3] = a0.w;
            a[4] = a1.x; a[5] = a1.y; a[6] = a1.z; a[7] = a1.w;
            unsigned long long b2[4];
            const unsigned long long* bp2 =
                reinterpret_cast<const unsigned long long*>(&Bs[k * 128 + tx * 8]);
            b2[0] = bp2[0]; b2[1] = bp2[1]; b2[2] = bp2[2]; b2[3] = bp2[3];
#pragma unroll
            for (int i = 0; i < 8; i++) {
                unsigned long long a2 = pk2(a[i], a[i]);
#pragma unroll
                for (int j = 0; j < 4; j++) ffma2(acc[i][j], a2, b2[j]);
            }
        }
        __syncthreads();
    }

    if (MODE <= 1) {
        float* outp = (MODE == 0) ? g_Y : g_T;
#pragma unroll
        for (int i = 0; i < 8; i++) {
            int m = m0 + ty * 8 + i;
            float r[8];
#pragma unroll
            for (int j = 0; j < 4; j++) {
                float lo, hi;
                upk2(acc[i][j], lo, hi);
                int c = j0 + tx * 8 + j * 2;
                r[2 * j]     = lrelu(lo + bias[c]);
                r[2 * j + 1] = lrelu(hi + bias[c + 1]);
            }
            float4* op = reinterpret_cast<float4*>(outp + (size_t)m * Dd + j0 + tx * 8);
            op[0] = make_float4(r[0], r[1], r[2], r[3]);
            op[1] = make_float4(r[4], r[5], r[6], r[7]);
        }
    } else {
        // Fused epilogue: lrelu + weighted reduction over h within this column tile
        float s[8];
#pragma unroll
        for (int i = 0; i < 8; i++) {
            s[i] = 0.0f;
#pragma unroll
            for (int j = 0; j < 4; j++) {
                float lo, hi;
                upk2(acc[i][j], lo, hi);
                int c = j0 + tx * 8 + j * 2;
                s[i] += lrelu(lo + biasp[c]) * wc2n[c];
                s[i] += lrelu(hi + biasp[c + 1]) * wc2n[c + 1];
            }
        }
        __shared__ float red[16][128];
#pragma unroll
        for (int i = 0; i < 8; i++) red[tx][ty * 8 + i] = s[i];
        __syncthreads();
        if (t < 128) {
            float tot = 0.0f;
#pragma unroll
            for (int q = 0; q < 16; q++) tot += red[q][t];
            atomicAdd(&g_logits[(size_t)(m0 + t) * Nn + n], tot);
        }
    }
}

// ---------------------------------------------------------------------------
// Finalize: full_out = logits + bc2 ;  out = sigmoid(diagonal gather)
// d_out layout: [0, 16384)  -> out (B,1,N) ; [16384, 278528) -> full_out (M,1,N)
// ---------------------------------------------------------------------------
__global__ void k_finalize(const float* __restrict__ bc2, float* __restrict__ out) {
    int i = blockIdx.x * blockDim.x + threadIdx.x;
    if (i >= M_TOT * Nn) return;
    int n = i & 15;
    out[16384 + i] = g_logits[i] + bc2[n];
    if (i < 16384) {
        int b = i >> 4;
        float lg = g_logits[((n * Bsz + b) << 4) + n] + bc2[n];
        out[i] = 1.0f / (1.0f + expf(-lg));
    }
}

// ---------------------------------------------------------------------------
extern "C" void kernel_launch(void* const* d_in, const int* in_sizes, int n_in,
                              void* d_out, int out_size) {
    const float* x   = (const float*)d_in[0];
    const float* Ws1 = (const float*)d_in[1];
    const float* bs1 = (const float*)d_in[2];
    const float* Ws2 = (const float*)d_in[3];
    const float* bs2 = (const float*)d_in[4];
    const float* Wc1 = (const float*)d_in[5];
    const float* bc1 = (const float*)d_in[6];
    const float* Wc2 = (const float*)d_in[7];
    const float* bc2 = (const float*)d_in[8];
    float* out = (float*)d_out;

    k_transpose<<<Bsz, 256>>>(x);
    k_gemm<0><<<dim3(4, 128, 1), 256>>>(Ws1, bs1, nullptr);
    k_gemm<1><<<dim3(4, 128, 1), 256>>>(Ws2, bs2, nullptr);
    k_zero<<<(M_TOT * Nn + 255) / 256, 256>>>();
    k_gemm<2><<<dim3(4, 128, 16), 256>>>(Wc1, bc1, Wc2);
    k_finalize<<<(M_TOT * Nn + 255) / 256, 256>>>(bc2, out);
}

// round 3
// speedup vs baseline: 2.0703x; 2.0703x over previous
#include <cuda_runtime.h>
#include <cuda_bf16.h>
#include <cstdint>
#include <math.h>

#define Bsz 1024
#define Dd  512
#define Nn  16
#define Hh  512
#define M_TOT 16384
#define KP  1536                 // split-bf16 widened K
#define KS  64                   // K per pipeline stage
#define NCH (KP / KS)            // 24
#define TM  256
#define TN  128
#define ROWB 144                 // smem row stride bytes (64 bf16 data + 16B pad)
#define STG_A (TM * ROWB)        // 36864
#define STG_B (TN * ROWB)        // 18432
#define STG   (STG_A + STG_B)    // 55296
#define SMEM_TOTAL (2 * STG)     // 110592

// ---------------- scratch (static device memory) ----------------
__device__ __nv_bfloat16 g_A0[(size_t)M_TOT * KP];
__device__ __nv_bfloat16 g_A1[(size_t)M_TOT * KP];
__device__ __nv_bfloat16 g_W1[(size_t)Dd * KP];
__device__ __nv_bfloat16 g_W2[(size_t)Dd * KP];
__device__ __nv_bfloat16 g_Wc[(size_t)Nn * Hh * KP];
__device__ float g_part[4 * (size_t)M_TOT * Nn];

// ---------------- helpers ----------------
static __device__ __forceinline__ uint32_t smem_u32(const void* p) {
    uint32_t a;
    asm("{ .reg .u64 t; cvta.to.shared.u64 t, %1; cvt.u32.u64 %0, t; }" : "=r"(a) : "l"(p));
    return a;
}
static __device__ __forceinline__ float lrelu(float v) { return v >= 0.0f ? v : 0.1f * v; }
static __device__ __forceinline__ void split2(float v, uint16_t& h, uint16_t& l) {
    __nv_bfloat16 hb = __float2bfloat16(v);
    __nv_bfloat16 lb = __float2bfloat16(v - __bfloat162float(hb));
    h = __bfloat16_as_ushort(hb);
    l = __bfloat16_as_ushort(lb);
}

#define LDSM4(r, a)                                                                     \
    asm volatile("ldmatrix.sync.aligned.m8n8.x4.shared.b16 {%0,%1,%2,%3}, [%4];"        \
                 : "=r"((r)[0]), "=r"((r)[1]), "=r"((r)[2]), "=r"((r)[3]) : "r"(a))
#define MMA(d, a, b0, b1)                                                               \
    asm volatile("mma.sync.aligned.m16n8k16.row.col.f32.bf16.bf16.f32 "                 \
                 "{%0,%1,%2,%3},{%4,%5,%6,%7},{%8,%9},{%0,%1,%2,%3};"                   \
                 : "+f"((d)[0]), "+f"((d)[1]), "+f"((d)[2]), "+f"((d)[3])               \
                 : "r"((a)[0]), "r"((a)[1]), "r"((a)[2]), "r"((a)[3]), "r"(b0), "r"(b1))
#define CPA(dst, src) asm volatile("cp.async.cg.shared.global [%0], [%1], 16;" :: "r"(dst), "l"(src))
#define CPC()  asm volatile("cp.async.commit_group;" ::: "memory")
#define CPW1() asm volatile("cp.async.wait_group 1;" ::: "memory")
#define CPW0() asm volatile("cp.async.wait_group 0;" ::: "memory")

// ---------------------------------------------------------------------------
// convert x: (B, D, N) fp32 -> g_A0[m = n*B + b][k'] split-bf16 [hi | lo | hi]
// ---------------------------------------------------------------------------
__global__ void k_convert_x(const float* __restrict__ x) {
    __shared__ float sm[Dd * 17];
    int b = blockIdx.x;
    const float4* xp = reinterpret_cast<const float4*>(x + (size_t)b * Dd * Nn);
    for (int v = threadIdx.x; v < 2048; v += blockDim.x) {
        float4 q = xp[v];
        int d = v >> 2, n0 = (v & 3) * 4;
        sm[d * 17 + n0 + 0] = q.x; sm[d * 17 + n0 + 1] = q.y;
        sm[d * 17 + n0 + 2] = q.z; sm[d * 17 + n0 + 3] = q.w;
    }
    __syncthreads();
    for (int n = 0; n < Nn; n++) {
        uint16_t* row = reinterpret_cast<uint16_t*>(g_A0 + (size_t)(n * Bsz + b) * KP);
        for (int d = threadIdx.x; d < Dd; d += blockDim.x) {
            uint16_t h, l;
            split2(sm[d * 17 + n], h, l);
            row[d] = h; row[512 + d] = l; row[1024 + d] = h;
        }
    }
}

// ---------------------------------------------------------------------------
// convert weights W[k][j] -> B'[j][k'] = [hi | hi | lo] (transposed)
// z = 0: Ws1 ; z = 1: Ws2 ; z >= 2: Wc1[n = z-2]
// ---------------------------------------------------------------------------
__global__ void k_convert_w(const float* __restrict__ Ws1,
                            const float* __restrict__ Ws2,
                            const float* __restrict__ Wc1) {
    __shared__ float sm[32][33];
    int z = blockIdx.z;
    const float* in;
    uint16_t* out;
    if (z == 0)      { in = Ws1; out = reinterpret_cast<uint16_t*>(g_W1); }
    else if (z == 1) { in = Ws2; out = reinterpret_cast<uint16_t*>(g_W2); }
    else             { in = Wc1 + (size_t)(z - 2) * Dd * Hh;
                       out = reinterpret_cast<uint16_t*>(g_Wc + (size_t)(z - 2) * Hh * KP); }
    int k0 = blockIdx.x * 32, j0 = blockIdx.y * 32;
    int tx = threadIdx.x, ty = threadIdx.y;
#pragma unroll
    for (int i = 0; i < 4; i++) {
        int r = ty + i * 8;
        sm[r][tx] = in[(size_t)(k0 + r) * Dd + j0 + tx];
    }
    __syncthreads();
#pragma unroll
    for (int i = 0; i < 4; i++) {
        int r = ty + i * 8;               // local j
        float v = sm[tx][r];              // W[k0+tx][j0+r]
        uint16_t h, l;
        split2(v, h, l);
        uint16_t* row = out + (size_t)(j0 + r) * KP;
        row[k0 + tx] = h; row[512 + k0 + tx] = h; row[1024 + k0 + tx] = l;
    }
}

// ---------------------------------------------------------------------------
// HMMA GEMM: CTA 256x128, warp 64x64 (wm = wid&3, wn = wid>>2), K' = 1536
// MODE 0/1: Aout = split(lrelu(A @ B' + bias))
// MODE 2:   g_part[jt][m][n] = sum_{h in tile} lrelu(acc + bc1[n,h]) * Wc2[n,h]
// ---------------------------------------------------------------------------
template <int MODE>
__global__ void __launch_bounds__(256, 1)
k_mma(const __nv_bfloat16* __restrict__ Ag,
      const __nv_bfloat16* __restrict__ Bg,
      const float* __restrict__ bias,
      const float* __restrict__ wc2,
      __nv_bfloat16* __restrict__ Aout) {
    extern __shared__ char smem[];
    uint32_t sb = smem_u32(smem);
    int tid = threadIdx.x, lane = tid & 31, wid = tid >> 5;
    int wm = wid & 3, wn = wid >> 2;

    int jt = blockIdx.x;
    int n  = (MODE == 2) ? blockIdx.y : 0;
    int m0 = ((MODE == 2) ? blockIdx.z : blockIdx.y) * TM;
    int j0 = jt * TN;

    const __nv_bfloat16* Ap = Ag + (size_t)m0 * KP;
    const __nv_bfloat16* Bp = Bg + ((size_t)n * Hh + j0) * KP;

    float acc[4][8][4];
#pragma unroll
    for (int a = 0; a < 4; a++)
#pragma unroll
        for (int b = 0; b < 8; b++)
#pragma unroll
            for (int c = 0; c < 4; c++) acc[a][b][c] = 0.0f;

    // ldmatrix per-lane offsets (stage-base and kk added later)
    uint32_t a_off[4], b_off[4];
#pragma unroll
    for (int mi = 0; mi < 4; mi++)
        a_off[mi] = (uint32_t)((wm * 64 + mi * 16 + (lane & 15)) * ROWB + (lane >> 4) * 16);
#pragma unroll
    for (int np = 0; np < 4; np++)
        b_off[np] = (uint32_t)(STG_A + (wn * 64 + np * 16 + (lane & 15)) * ROWB + (lane >> 4) * 16);

    // ---- stage 0 loads ----
    {
        uint32_t base = sb;
#pragma unroll
        for (int i = 0; i < 8; i++) {
            int idx = tid + i * 256, row = idx >> 3, seg = idx & 7;
            CPA(base + row * ROWB + seg * 16, Ap + (size_t)row * KP + seg * 8);
        }
#pragma unroll
        for (int i = 0; i < 4; i++) {
            int idx = tid + i * 256, row = idx >> 3, seg = idx & 7;
            CPA(base + STG_A + row * ROWB + seg * 16, Bp + (size_t)row * KP + seg * 8);
        }
        CPC();
    }

    for (int c = 0; c < NCH; c++) {
        if (c + 1 < NCH) {
            uint32_t base = sb + ((c + 1) & 1) * STG;
            int koff = (c + 1) * KS;
#pragma unroll
            for (int i = 0; i < 8; i++) {
                int idx = tid + i * 256, row = idx >> 3, seg = idx & 7;
                CPA(base + row * ROWB + seg * 16, Ap + (size_t)row * KP + koff + seg * 8);
            }
#pragma unroll
            for (int i = 0; i < 4; i++) {
                int idx = tid + i * 256, row = idx >> 3, seg = idx & 7;
                CPA(base + STG_A + row * ROWB + seg * 16, Bp + (size_t)row * KP + koff + seg * 8);
            }
            CPC();
            CPW1();
        } else {
            CPW0();
        }
        __syncthreads();
        uint32_t base = sb + (c & 1) * STG;
#pragma unroll
        for (int kk = 0; kk < 4; kk++) {
            uint32_t a[4][4], b[4][4];
#pragma unroll
            for (int mi = 0; mi < 4; mi++) LDSM4(a[mi], base + a_off[mi] + kk * 32);
#pragma unroll
            for (int np = 0; np < 4; np++) LDSM4(b[np], base + b_off[np] + kk * 32);
#pragma unroll
            for (int mi = 0; mi < 4; mi++)
#pragma unroll
                for (int np = 0; np < 4; np++) {
                    MMA(acc[mi][2 * np],     a[mi], b[np][0], b[np][2]);
                    MMA(acc[mi][2 * np + 1], a[mi], b[np][1], b[np][3]);
                }
        }
        __syncthreads();
    }

    if (MODE <= 1) {
#pragma unroll
        for (int mi = 0; mi < 4; mi++)
#pragma unroll
            for (int half = 0; half < 2; half++) {
                int row = m0 + wm * 64 + mi * 16 + (lane >> 2) + half * 8;
                __nv_bfloat16* rowp = Aout + (size_t)row * KP;
#pragma unroll
                for (int ni = 0; ni < 8; ni++) {
                    int col = j0 + wn * 64 + ni * 8 + (lane & 3) * 2;
                    float v0 = lrelu(acc[mi][ni][half * 2]     + __ldg(&bias[col]));
                    float v1 = lrelu(acc[mi][ni][half * 2 + 1] + __ldg(&bias[col + 1]));
                    uint16_t h0, l0, h1, l1;
                    split2(v0, h0, l0);
                    split2(v1, h1, l1);
                    uint32_t hp = (uint32_t)h0 | ((uint32_t)h1 << 16);
                    uint32_t lp = (uint32_t)l0 | ((uint32_t)l1 << 16);
                    *reinterpret_cast<uint32_t*>(rowp + col)        = hp;
                    *reinterpret_cast<uint32_t*>(rowp + 512 + col)  = lp;
                    *reinterpret_cast<uint32_t*>(rowp + 1024 + col) = hp;
                }
            }
    } else {
        float rs[4][2];
#pragma unroll
        for (int mi = 0; mi < 4; mi++)
#pragma unroll
            for (int half = 0; half < 2; half++) {
                float s = 0.0f;
#pragma unroll
                for (int ni = 0; ni < 8; ni++) {
                    int col = j0 + wn * 64 + ni * 8 + (lane & 3) * 2;
                    int bi = n * Hh + col;
                    s += lrelu(acc[mi][ni][half * 2]     + __ldg(&bias[bi]))     * __ldg(&wc2[bi]);
                    s += lrelu(acc[mi][ni][half * 2 + 1] + __ldg(&bias[bi + 1])) * __ldg(&wc2[bi + 1]);
                }
                s += __shfl_xor_sync(0xffffffffu, s, 1);
                s += __shfl_xor_sync(0xffffffffu, s, 2);
                rs[mi][half] = s;
            }
        float* red = reinterpret_cast<float*>(smem);   // loop ended with __syncthreads
        if ((lane & 3) == 0) {
#pragma unroll
            for (int mi = 0; mi < 4; mi++)
#pragma unroll
                for (int half = 0; half < 2; half++) {
                    int rl = wm * 64 + mi * 16 + (lane >> 2) + half * 8;
                    red[wn * 256 + rl] = rs[mi][half];
                }
        }
        __syncthreads();
        if (tid < 256) {
            float tot = red[tid] + red[256 + tid];
            g_part[((size_t)jt * M_TOT + m0 + tid) * Nn + n] = tot;
        }
    }
}

// ---------------------------------------------------------------------------
// finalize: full_out[m][n] = sum_jt part + bc2 ; diag sigmoid for out
// ---------------------------------------------------------------------------
__global__ void k_fin(const float* __restrict__ bc2, float* __restrict__ out) {
    int i = blockIdx.x * blockDim.x + threadIdx.x;
    if (i >= M_TOT * Nn) return;
    int nn = i & 15;
    float lg = g_part[i] + g_part[262144 + i] + g_part[2 * 262144 + i] + g_part[3 * 262144 + i]
             + bc2[nn];
    out[16384 + i] = lg;
}
__global__ void k_sig(const float* __restrict__ bc2, float* __restrict__ out) {
    int i = blockIdx.x * blockDim.x + threadIdx.x;
    if (i >= Bsz * Nn) return;
    int b = i >> 4, nn = i & 15;
    size_t idx = ((size_t)nn * Bsz + b) * Nn + nn;
    float lg = g_part[idx] + g_part[262144 + idx] + g_part[2 * 262144 + idx]
             + g_part[3 * 262144 + idx] + bc2[nn];
    out[i] = 1.0f / (1.0f + expf(-lg));
}

// ---------------------------------------------------------------------------
extern "C" void kernel_launch(void* const* d_in, const int* in_sizes, int n_in,
                              void* d_out, int out_size) {
    const float* x   = (const float*)d_in[0];
    const float* Ws1 = (const float*)d_in[1];
    const float* bs1 = (const float*)d_in[2];
    const float* Ws2 = (const float*)d_in[3];
    const float* bs2 = (const float*)d_in[4];
    const float* Wc1 = (const float*)d_in[5];
    const float* bc1 = (const float*)d_in[6];
    const float* Wc2 = (const float*)d_in[7];
    const float* bc2 = (const float*)d_in[8];
    float* out = (float*)d_out;

    cudaFuncSetAttribute(k_mma<0>, cudaFuncAttributeMaxDynamicSharedMemorySize, SMEM_TOTAL);
    cudaFuncSetAttribute(k_mma<1>, cudaFuncAttributeMaxDynamicSharedMemorySize, SMEM_TOTAL);
    cudaFuncSetAttribute(k_mma<2>, cudaFuncAttributeMaxDynamicSharedMemorySize, SMEM_TOTAL);

    __nv_bfloat16 *A0p, *A1p, *W1p, *W2p, *Wcp;
    cudaGetSymbolAddress((void**)&A0p, g_A0);
    cudaGetSymbolAddress((void**)&A1p, g_A1);
    cudaGetSymbolAddress((void**)&W1p, g_W1);
    cudaGetSymbolAddress((void**)&W2p, g_W2);
    cudaGetSymbolAddress((void**)&Wcp, g_Wc);

    k_convert_x<<<Bsz, 256>>>(x);
    k_convert_w<<<dim3(16, 16, 18), dim3(32, 8)>>>(Ws1, Ws2, Wc1);

    k_mma<0><<<dim3(4, 64), 256, SMEM_TOTAL>>>(A0p, W1p, bs1, nullptr, A1p);
    k_mma<1><<<dim3(4, 64), 256, SMEM_TOTAL>>>(A1p, W2p, bs2, nullptr, A0p);
    k_mma<2><<<dim3(4, 16, 64), 256, SMEM_TOTAL>>>(A0p, Wcp, bc1, Wc2, nullptr);

    k_fin<<<(M_TOT * Nn + 255) / 256, 256>>>(bc2, out);
    k_sig<<<(Bsz * Nn + 255) / 256, 256>>>(bc2, out);
}

// round 4
// speedup vs baseline: 2.1885x; 1.0571x over previous
#include <cuda_runtime.h>
#include <cuda_bf16.h>
#include <cstdint>
#include <math.h>

#define Bsz 1024
#define Dd  512
#define Nn  16
#define Hh  512
#define M_TOT 16384
#define KP  1536                 // split-bf16 widened K
#define KS  64                   // K per pipeline stage
#define NCH (KP / KS)            // 24
#define TM  128
#define TN  128
#define ROWB 144                 // smem row stride bytes (64 bf16 + 16B pad)
#define STG_A (TM * ROWB)        // 18432
#define STG_B (TN * ROWB)        // 18432
#define STG   (STG_A + STG_B)    // 36864
#define NSTAGE 3
#define SMEM_TOTAL (NSTAGE * STG)   // 110592

// ---------------- scratch (static device memory) ----------------
__device__ __nv_bfloat16 g_A0[(size_t)M_TOT * KP];
__device__ __nv_bfloat16 g_A1[(size_t)M_TOT * KP];
__device__ __nv_bfloat16 g_W1[(size_t)Dd * KP];
__device__ __nv_bfloat16 g_W2[(size_t)Dd * KP];
__device__ __nv_bfloat16 g_Wc[(size_t)Nn * Hh * KP];
__device__ float g_part[4 * (size_t)M_TOT * Nn];

// ---------------- helpers ----------------
static __device__ __forceinline__ uint32_t smem_u32(const void* p) {
    uint32_t a;
    asm("{ .reg .u64 t; cvta.to.shared.u64 t, %1; cvt.u32.u64 %0, t; }" : "=r"(a) : "l"(p));
    return a;
}
static __device__ __forceinline__ float lrelu(float v) { return v >= 0.0f ? v : 0.1f * v; }
static __device__ __forceinline__ void split2(float v, uint16_t& h, uint16_t& l) {
    __nv_bfloat16 hb = __float2bfloat16(v);
    __nv_bfloat16 lb = __float2bfloat16(v - __bfloat162float(hb));
    h = __bfloat16_as_ushort(hb);
    l = __bfloat16_as_ushort(lb);
}

#define LDSM4(r, a)                                                                     \
    asm volatile("ldmatrix.sync.aligned.m8n8.x4.shared.b16 {%0,%1,%2,%3}, [%4];"        \
                 : "=r"((r)[0]), "=r"((r)[1]), "=r"((r)[2]), "=r"((r)[3]) : "r"(a))
#define MMA(d, a, b0, b1)                                                               \
    asm volatile("mma.sync.aligned.m16n8k16.row.col.f32.bf16.bf16.f32 "                 \
                 "{%0,%1,%2,%3},{%4,%5,%6,%7},{%8,%9},{%0,%1,%2,%3};"                   \
                 : "+f"((d)[0]), "+f"((d)[1]), "+f"((d)[2]), "+f"((d)[3])               \
                 : "r"((a)[0]), "r"((a)[1]), "r"((a)[2]), "r"((a)[3]), "r"(b0), "r"(b1))
#define CPA(dst, src) asm volatile("cp.async.cg.shared.global [%0], [%1], 16;" :: "r"(dst), "l"(src))
#define CPC()  asm volatile("cp.async.commit_group;" ::: "memory")
#define CPW1() asm volatile("cp.async.wait_group 1;" ::: "memory")
#define CPW0() asm volatile("cp.async.wait_group 0;" ::: "memory")

// ---------------------------------------------------------------------------
// convert x: (B, D, N) fp32 -> g_A0[m = n*B + b][k'] split-bf16 [hi | lo | hi]
// ---------------------------------------------------------------------------
__global__ void k_convert_x(const float* __restrict__ x) {
    __shared__ float sm[Dd * 17];
    int b = blockIdx.x;
    const float4* xp = reinterpret_cast<const float4*>(x + (size_t)b * Dd * Nn);
    for (int v = threadIdx.x; v < 2048; v += blockDim.x) {
        float4 q = xp[v];
        int d = v >> 2, n0 = (v & 3) * 4;
        sm[d * 17 + n0 + 0] = q.x; sm[d * 17 + n0 + 1] = q.y;
        sm[d * 17 + n0 + 2] = q.z; sm[d * 17 + n0 + 3] = q.w;
    }
    __syncthreads();
    for (int n = 0; n < Nn; n++) {
        uint16_t* row = reinterpret_cast<uint16_t*>(g_A0 + (size_t)(n * Bsz + b) * KP);
        for (int d = threadIdx.x; d < Dd; d += blockDim.x) {
            uint16_t h, l;
            split2(sm[d * 17 + n], h, l);
            row[d] = h; row[512 + d] = l; row[1024 + d] = h;
        }
    }
}

// ---------------------------------------------------------------------------
// convert weights W[k][j] -> B'[j][k'] = [hi | hi | lo] (transposed)
// ---------------------------------------------------------------------------
__global__ void k_convert_w(const float* __restrict__ Ws1,
                            const float* __restrict__ Ws2,
                            const float* __restrict__ Wc1) {
    __shared__ float sm[32][33];
    int z = blockIdx.z;
    const float* in;
    uint16_t* out;
    if (z == 0)      { in = Ws1; out = reinterpret_cast<uint16_t*>(g_W1); }
    else if (z == 1) { in = Ws2; out = reinterpret_cast<uint16_t*>(g_W2); }
    else             { in = Wc1 + (size_t)(z - 2) * Dd * Hh;
                       out = reinterpret_cast<uint16_t*>(g_Wc + (size_t)(z - 2) * Hh * KP); }
    int k0 = blockIdx.x * 32, j0 = blockIdx.y * 32;
    int tx = threadIdx.x, ty = threadIdx.y;
#pragma unroll
    for (int i = 0; i < 4; i++) {
        int r = ty + i * 8;
        sm[r][tx] = in[(size_t)(k0 + r) * Dd + j0 + tx];
    }
    __syncthreads();
#pragma unroll
    for (int i = 0; i < 4; i++) {
        int r = ty + i * 8;
        float v = sm[tx][r];
        uint16_t h, l;
        split2(v, h, l);
        uint16_t* row = out + (size_t)(j0 + r) * KP;
        row[k0 + tx] = h; row[512 + k0 + tx] = h; row[1024 + k0 + tx] = l;
    }
}

// ---------------------------------------------------------------------------
// HMMA GEMM: CTA 128x128, warp 64x32 (wm = wid&1, wn = wid>>1), K' = 1536
// 3-stage cp.async pipeline, one barrier per K-chunk, 2 CTAs/SM.
// MODE 0/1: Aout = split(lrelu(A @ B' + bias))
// MODE 2:   g_part[jt][m][n] = sum_{h in tile} lrelu(acc + bc1[n,h]) * Wc2[n,h]
// ---------------------------------------------------------------------------
template <int MODE>
__global__ void __launch_bounds__(256, 2)
k_mma(const __nv_bfloat16* __restrict__ Ag,
      const __nv_bfloat16* __restrict__ Bg,
      const float* __restrict__ bias,
      const float* __restrict__ wc2,
      __nv_bfloat16* __restrict__ Aout) {
    extern __shared__ char smem[];
    uint32_t sb = smem_u32(smem);
    int tid = threadIdx.x, lane = tid & 31, wid = tid >> 5;
    int wm = wid & 1, wn = wid >> 1;

    int jt = blockIdx.x;
    int n  = (MODE == 2) ? blockIdx.y : 0;
    int m0 = ((MODE == 2) ? blockIdx.z : blockIdx.y) * TM;
    int j0 = jt * TN;

    const __nv_bfloat16* Ap = Ag + (size_t)m0 * KP;
    const __nv_bfloat16* Bp = Bg + ((size_t)n * Hh + j0) * KP;

    float acc[4][4][4];
#pragma unroll
    for (int a = 0; a < 4; a++)
#pragma unroll
        for (int b = 0; b < 4; b++)
#pragma unroll
            for (int c = 0; c < 4; c++) acc[a][b][c] = 0.0f;

    uint32_t a_off[4], b_off[2];
#pragma unroll
    for (int mi = 0; mi < 4; mi++)
        a_off[mi] = (uint32_t)((wm * 64 + mi * 16 + (lane & 15)) * ROWB + (lane >> 4) * 16);
#pragma unroll
    for (int np = 0; np < 2; np++)
        b_off[np] = (uint32_t)(STG_A + (wn * 32 + np * 16 + (lane & 15)) * ROWB + (lane >> 4) * 16);

    // ---- prologue: stages 0 and 1 ----
#pragma unroll
    for (int s = 0; s < 2; s++) {
        uint32_t base = sb + s * STG;
        int koff = s * KS;
#pragma unroll
        for (int i = 0; i < 4; i++) {
            int idx = tid + i * 256, row = idx >> 3, seg = idx & 7;
            CPA(base + row * ROWB + seg * 16, Ap + (size_t)row * KP + koff + seg * 8);
        }
#pragma unroll
        for (int i = 0; i < 4; i++) {
            int idx = tid + i * 256, row = idx >> 3, seg = idx & 7;
            CPA(base + STG_A + row * ROWB + seg * 16, Bp + (size_t)row * KP + koff + seg * 8);
        }
        CPC();
    }

    int sbuf = 0;                      // stage index of chunk c, cycles 0,1,2
    int wbuf = 2;                      // stage index to write (c+2)
    for (int c = 0; c < NCH; c++) {
        if (c == NCH - 1) { CPW0(); } else { CPW1(); }
        __syncthreads();               // data of chunk c visible; buffer wbuf free
        if (c + 2 < NCH) {
            uint32_t base = sb + wbuf * STG;
            int koff = (c + 2) * KS;
#pragma unroll
            for (int i = 0; i < 4; i++) {
                int idx = tid + i * 256, row = idx >> 3, seg = idx & 7;
                CPA(base + row * ROWB + seg * 16, Ap + (size_t)row * KP + koff + seg * 8);
            }
#pragma unroll
            for (int i = 0; i < 4; i++) {
                int idx = tid + i * 256, row = idx >> 3, seg = idx & 7;
                CPA(base + STG_A + row * ROWB + seg * 16, Bp + (size_t)row * KP + koff + seg * 8);
            }
            CPC();
        }
        uint32_t base = sb + sbuf * STG;
#pragma unroll
        for (int kk = 0; kk < 4; kk++) {
            uint32_t a[4][4], b[2][4];
#pragma unroll
            for (int mi = 0; mi < 4; mi++) LDSM4(a[mi], base + a_off[mi] + kk * 32);
#pragma unroll
            for (int np = 0; np < 2; np++) LDSM4(b[np], base + b_off[np] + kk * 32);
#pragma unroll
            for (int mi = 0; mi < 4; mi++)
#pragma unroll
                for (int np = 0; np < 2; np++) {
                    MMA(acc[mi][2 * np],     a[mi], b[np][0], b[np][2]);
                    MMA(acc[mi][2 * np + 1], a[mi], b[np][1], b[np][3]);
                }
        }
        sbuf = (sbuf == 2) ? 0 : sbuf + 1;
        wbuf = (wbuf == 2) ? 0 : wbuf + 1;
    }

    if (MODE <= 1) {
#pragma unroll
        for (int mi = 0; mi < 4; mi++)
#pragma unroll
            for (int half = 0; half < 2; half++) {
                int row = m0 + wm * 64 + mi * 16 + (lane >> 2) + half * 8;
                __nv_bfloat16* rowp = Aout + (size_t)row * KP;
#pragma unroll
                for (int ni = 0; ni < 4; ni++) {
                    int col = j0 + wn * 32 + ni * 8 + (lane & 3) * 2;
                    float v0 = lrelu(acc[mi][ni][half * 2]     + __ldg(&bias[col]));
                    float v1 = lrelu(acc[mi][ni][half * 2 + 1] + __ldg(&bias[col + 1]));
                    uint16_t h0, l0, h1, l1;
                    split2(v0, h0, l0);
                    split2(v1, h1, l1);
                    uint32_t hp = (uint32_t)h0 | ((uint32_t)h1 << 16);
                    uint32_t lp = (uint32_t)l0 | ((uint32_t)l1 << 16);
                    *reinterpret_cast<uint32_t*>(rowp + col)        = hp;
                    *reinterpret_cast<uint32_t*>(rowp + 512 + col)  = lp;
                    *reinterpret_cast<uint32_t*>(rowp + 1024 + col) = hp;
                }
            }
    } else {
        float rs[4][2];
#pragma unroll
        for (int mi = 0; mi < 4; mi++)
#pragma unroll
            for (int half = 0; half < 2; half++) {
                float s = 0.0f;
#pragma unroll
                for (int ni = 0; ni < 4; ni++) {
                    int col = j0 + wn * 32 + ni * 8 + (lane & 3) * 2;
                    int bi = n * Hh + col;
                    s += lrelu(acc[mi][ni][half * 2]     + __ldg(&bias[bi]))     * __ldg(&wc2[bi]);
                    s += lrelu(acc[mi][ni][half * 2 + 1] + __ldg(&bias[bi + 1])) * __ldg(&wc2[bi + 1]);
                }
                s += __shfl_xor_sync(0xffffffffu, s, 1);
                s += __shfl_xor_sync(0xffffffffu, s, 2);
                rs[mi][half] = s;
            }
        __syncthreads();
        float* red = reinterpret_cast<float*>(smem);
        if ((lane & 3) == 0) {
#pragma unroll
            for (int mi = 0; mi < 4; mi++)
#pragma unroll
                for (int half = 0; half < 2; half++) {
                    int rl = wm * 64 + mi * 16 + (lane >> 2) + half * 8;
                    red[wn * 128 + rl] = rs[mi][half];
                }
        }
        __syncthreads();
        if (tid < 128) {
            float tot = red[tid] + red[128 + tid] + red[256 + tid] + red[384 + tid];
            g_part[((size_t)jt * M_TOT + m0 + tid) * Nn + n] = tot;
        }
    }
}

// ---------------------------------------------------------------------------
__global__ void k_fin(const float* __restrict__ bc2, float* __restrict__ out) {
    int i = blockIdx.x * blockDim.x + threadIdx.x;
    if (i >= M_TOT * Nn) return;
    int nn = i & 15;
    float lg = g_part[i] + g_part[262144 + i] + g_part[2 * 262144 + i] + g_part[3 * 262144 + i]
             + bc2[nn];
    out[16384 + i] = lg;
}
__global__ void k_sig(const float* __restrict__ bc2, float* __restrict__ out) {
    int i = blockIdx.x * blockDim.x + threadIdx.x;
    if (i >= Bsz * Nn) return;
    int b = i >> 4, nn = i & 15;
    size_t idx = ((size_t)nn * Bsz + b) * Nn + nn;
    float lg = g_part[idx] + g_part[262144 + idx] + g_part[2 * 262144 + idx]
             + g_part[3 * 262144 + idx] + bc2[nn];
    out[i] = 1.0f / (1.0f + expf(-lg));
}

// ---------------------------------------------------------------------------
extern "C" void kernel_launch(void* const* d_in, const int* in_sizes, int n_in,
                              void* d_out, int out_size) {
    const float* x   = (const float*)d_in[0];
    const float* Ws1 = (const float*)d_in[1];
    const float* bs1 = (const float*)d_in[2];
    const float* Ws2 = (const float*)d_in[3];
    const float* bs2 = (const float*)d_in[4];
    const float* Wc1 = (const float*)d_in[5];
    const float* bc1 = (const float*)d_in[6];
    const float* Wc2 = (const float*)d_in[7];
    const float* bc2 = (const float*)d_in[8];
    float* out = (float*)d_out;

    cudaFuncSetAttribute(k_mma<0>, cudaFuncAttributeMaxDynamicSharedMemorySize, SMEM_TOTAL);
    cudaFuncSetAttribute(k_mma<1>, cudaFuncAttributeMaxDynamicSharedMemorySize, SMEM_TOTAL);
    cudaFuncSetAttribute(k_mma<2>, cudaFuncAttributeMaxDynamicSharedMemorySize, SMEM_TOTAL);

    __nv_bfloat16 *A0p, *A1p, *W1p, *W2p, *Wcp;
    cudaGetSymbolAddress((void**)&A0p, g_A0);
    cudaGetSymbolAddress((void**)&A1p, g_A1);
    cudaGetSymbolAddress((void**)&W1p, g_W1);
    cudaGetSymbolAddress((void**)&W2p, g_W2);
    cudaGetSymbolAddress((void**)&Wcp, g_Wc);

    k_convert_x<<<Bsz, 256>>>(x);
    k_convert_w<<<dim3(16, 16, 18), dim3(32, 8)>>>(Ws1, Ws2, Wc1);

    k_mma<0><<<dim3(4, 128), 256, SMEM_TOTAL>>>(A0p, W1p, bs1, nullptr, A1p);
    k_mma<1><<<dim3(4, 128), 256, SMEM_TOTAL>>>(A1p, W2p, bs2, nullptr, A0p);
    k_mma<2><<<dim3(4, 16, 128), 256, SMEM_TOTAL>>>(A0p, Wcp, bc1, Wc2, nullptr);

    k_fin<<<(M_TOT * Nn + 255) / 256, 256>>>(bc2, out);
    k_sig<<<(Bsz * Nn + 255) / 256, 256>>>(bc2, out);
}